// round 6
// baseline (speedup 1.0000x reference)
#include <cuda_runtime.h>
#include <cuda_bf16.h>
#include <cstddef>
#include <math.h>

#define BATCH 256
#define TT    2048
#define HID   128
#define G4    512           // 4*HID
#define MROWS (BATCH*TT)    // 524288

// ---- scratch (static device arrays: sanctioned allocation-free path) ----
__device__ float g_out0[(size_t)MROWS * HID];   // layer0 hidden states [B*T, 128]
__device__ float g_xg1 [(size_t)MROWS * G4];    // layer1 input gates (+bias) [B*T, 512]

// ---------------------------------------------------------------------------
// Recurrent LSTM layer. 128 CTAs x 512 threads; CTA owns batch rows 2*bx, 2*bx+1.
// Thread g computes gate-row g for both batch rows. W_hh cols [0,96) in smem
// (float2, k-major -> conflict-free), cols [96,128) in registers.
// h broadcast from smem via float4. Two __syncthreads per step.
// ---------------------------------------------------------------------------
#define KSM 96
#define KRG 32
#define SMEM_LSTM ((KSM/2)*G4*8 /*Wsm float2*/ + 2*HID*4 /*h*/ + 2*G4*4 /*gates*/)

template<int LAYER>
__global__ void __launch_bounds__(512, 1)
lstm_kernel(const float* __restrict__ x,     // layer0: [B,T,1]
            const float* __restrict__ W_ih,  // layer0: [512,1]
            const float* __restrict__ W_hh,  // [512,128]
            const float* __restrict__ b_ih,
            const float* __restrict__ b_hh,
            const float* __restrict__ W_fc,  // layer1: [1,128]
            const float* __restrict__ b_fc,  // layer1: [1]
            float* __restrict__ out)
{
    extern __shared__ float sm[];
    float2* Wsm     = (float2*)sm;                    // [48][512] float2
    float*  h_sm    = sm + (KSM/2) * G4 * 2;          // [2][128]
    float*  gate_sm = h_sm + 2 * HID;                 // [2][512]

    const int g  = threadIdx.x;
    const int b0 = blockIdx.x * 2;

    // Load W_hh cols [0,96): Wsm[k2][g] = (W[g][2k2], W[g][2k2+1])
    #pragma unroll 4
    for (int k2 = 0; k2 < KSM/2; k2++) {
        float wx = __ldg(&W_hh[g * HID + 2*k2]);
        float wy = __ldg(&W_hh[g * HID + 2*k2 + 1]);
        Wsm[k2 * G4 + g] = make_float2(wx, wy);
    }
    // Cols [96,128) in registers
    float wreg[KRG];
    #pragma unroll
    for (int i = 0; i < KRG; i++)
        wreg[i] = __ldg(&W_hh[g * HID + KSM + i]);

    float wih = 0.f, bias = 0.f;
    if (LAYER == 0) {
        wih  = __ldg(&W_ih[g]);
        bias = __ldg(&b_ih[g]) + __ldg(&b_hh[g]);
    }

    if (g < 2 * HID) h_sm[g] = 0.f;
    float c = 0.f;                       // cell state for update threads (g<256)
    __syncthreads();

    const float4* h4a = (const float4*)h_sm;            // batch row 0, 32 float4
    const float4* h4b = (const float4*)(h_sm + HID);    // batch row 1
    const int ub = g >> 7;               // update thread: batch slot (valid g<256)
    const int uj = g & (HID - 1);
    const int gclass = g >> 7;           // 0:i 1:f 2:g 3:o  (warp-uniform)

    for (int t = 0; t < TT; t++) {
        // --- input-gate contribution (issued early, consumed after the dot) ---
        float a0, a1;
        if (LAYER == 0) {
            float xv0 = __ldg(&x[(size_t)b0 * TT + t]);
            float xv1 = __ldg(&x[(size_t)(b0 + 1) * TT + t]);
            a0 = fmaf(wih, xv0, bias);
            a1 = fmaf(wih, xv1, bias);
        } else {
            a0 = __ldg(&g_xg1[((size_t)b0 * TT + t) * G4 + g]);
            a1 = __ldg(&g_xg1[((size_t)(b0 + 1) * TT + t) * G4 + g]);
        }

        // --- recurrent dot: gates += W_hh[g,:] . h[b,:] ---
        #pragma unroll
        for (int k4 = 0; k4 < KSM/4; k4++) {          // k = 4*k4 .. 4*k4+3
            float2 wA = Wsm[(2*k4)     * G4 + g];
            float2 wB = Wsm[(2*k4 + 1) * G4 + g];
            float4 h0 = h4a[k4];
            float4 h1 = h4b[k4];
            a0 = fmaf(wA.x, h0.x, a0); a0 = fmaf(wA.y, h0.y, a0);
            a0 = fmaf(wB.x, h0.z, a0); a0 = fmaf(wB.y, h0.w, a0);
            a1 = fmaf(wA.x, h1.x, a1); a1 = fmaf(wA.y, h1.y, a1);
            a1 = fmaf(wB.x, h1.z, a1); a1 = fmaf(wB.y, h1.w, a1);
        }
        #pragma unroll
        for (int k4 = 0; k4 < KRG/4; k4++) {          // k = 96 + 4*k4 ..
            float4 h0 = h4a[KSM/4 + k4];
            float4 h1 = h4b[KSM/4 + k4];
            a0 = fmaf(wreg[4*k4+0], h0.x, a0); a0 = fmaf(wreg[4*k4+1], h0.y, a0);
            a0 = fmaf(wreg[4*k4+2], h0.z, a0); a0 = fmaf(wreg[4*k4+3], h0.w, a0);
            a1 = fmaf(wreg[4*k4+0], h1.x, a1); a1 = fmaf(wreg[4*k4+1], h1.y, a1);
            a1 = fmaf(wreg[4*k4+2], h1.z, a1); a1 = fmaf(wreg[4*k4+3], h1.w, a1);
        }

        // --- activation (i,f,o: sigmoid; g: tanh) ---
        float act0, act1;
        if (gclass == 2) {
            act0 = tanhf(a0);
            act1 = tanhf(a1);
        } else {
            act0 = 1.0f / (1.0f + expf(-a0));
            act1 = 1.0f / (1.0f + expf(-a1));
        }
        gate_sm[g]      = act0;
        gate_sm[G4 + g] = act1;
        __syncthreads();

        // --- cell/hidden update (threads 0..255; thread owns (ub, uj)) ---
        if (g < 2 * HID) {
            const float* gb = gate_sm + ub * G4;
            float iv = gb[uj];
            float fv = gb[HID + uj];
            float gv = gb[2*HID + uj];
            float ov = gb[3*HID + uj];
            c = fmaf(fv, c, iv * gv);
            float h = ov * tanhf(c);
            h_sm[ub * HID + uj] = h;
            if (LAYER == 0)
                g_out0[((size_t)(b0 + ub) * TT + t) * HID + uj] = h;
        }
        __syncthreads();
    }

    // --- final h_n / c_n ---
    // out layout: y[256] | h_n[2][256][128] | c_n[2][256][128]
    if (g < 2 * HID) {
        int bglob = b0 + ub;
        float h = h_sm[ub * HID + uj];
        out[256 + ((size_t)LAYER * BATCH + bglob) * HID + uj]          = h;
        out[256 + 2*BATCH*HID*1 + ((size_t)LAYER * BATCH + bglob) * HID + uj - (LAYER==LAYER ? 0 : 0)] = c; // placeholder avoided below
    }
    // (rewrite c_n cleanly; the line above wrote to the h_n+offset region incorrectly if misread—do it explicitly)
    if (g < 2 * HID) {
        int bglob = b0 + ub;
        out[256 + (size_t)BATCH * HID * 2 /*skip h_n [2,256,128]*/
                + ((size_t)LAYER * BATCH + bglob) * HID + uj] = c;
    }

    // --- FC head (layer 1 only): y[b] = h_final[b] . W_fc + b_fc ---
    if (LAYER == 1 && g < 64) {
        int w = g >> 5;          // 0 or 1 -> batch slot
        int l = g & 31;
        float s = 0.f;
        #pragma unroll
        for (int j = l; j < HID; j += 32)
            s = fmaf(h_sm[w * HID + j], __ldg(&W_fc[j]), s);
        #pragma unroll
        for (int off = 16; off > 0; off >>= 1)
            s += __shfl_down_sync(0xffffffffu, s, off);
        if (l == 0)
            out[b0 + w] = s + __ldg(&b_fc[0]);
    }
}

// ---------------------------------------------------------------------------
// GEMM: g_xg1[M,512] = g_out0[M,128] @ W_ih1^T + (b_ih1 + b_hh1)
// Tiles 128(M) x 64(N), K-chunks of 32. 256 threads, 8x4 register blocking.
// ---------------------------------------------------------------------------
__global__ void __launch_bounds__(256)
gemm_xg1_kernel(const float* __restrict__ W,     // W_ih_l1 [512,128]
                const float* __restrict__ b_ih,
                const float* __restrict__ b_hh)
{
    __shared__ float As[128][36];   // [m][k] row-major, +4 pad
    __shared__ float Bs[32][64];    // [k][n] transposed
    __shared__ float bias_s[64];

    const int tid = threadIdx.x;
    const int m0 = blockIdx.x * 128;
    const int n0 = blockIdx.y * 64;

    if (tid < 64)
        bias_s[tid] = __ldg(&b_ih[n0 + tid]) + __ldg(&b_hh[n0 + tid]);

    const int tx = tid & 15;        // N dir: cols tx*4 .. tx*4+3
    const int ty = tid >> 4;        // M dir: rows ty*8 .. ty*8+7

    const int ar = tid >> 1;        // A load: row 0..127
    const int ah = (tid & 1) * 16;  // A load: col offset 0/16 within chunk
    const int bn = tid & 63;        // B load: n row 0..63
    const int bq = tid >> 6;        // B load: k-quarter 0..3 (8 k each)

    float acc[8][4];
    #pragma unroll
    for (int i = 0; i < 8; i++)
        #pragma unroll
        for (int j = 0; j < 4; j++) acc[i][j] = 0.f;

    for (int kc = 0; kc < 128; kc += 32) {
        __syncthreads();
        // load A chunk: 128 rows x 32 cols (coalesced 128B per row-pair of lanes)
        {
            const float4* ap = (const float4*)(g_out0 + (size_t)(m0 + ar) * HID + kc + ah);
            float4 v0 = ap[0], v1 = ap[1], v2 = ap[2], v3 = ap[3];
            *(float4*)&As[ar][ah + 0]  = v0;
            *(float4*)&As[ar][ah + 4]  = v1;
            *(float4*)&As[ar][ah + 8]  = v2;
            *(float4*)&As[ar][ah + 12] = v3;
        }
        // load B chunk: 64 n-rows x 32 k, store transposed (conflict-free: bank = n%32)
        {
            const float4* bp = (const float4*)(W + (size_t)(n0 + bn) * HID + kc + bq * 8);
            float4 v0 = bp[0], v1 = bp[1];
            Bs[bq*8 + 0][bn] = v0.x; Bs[bq*8 + 1][bn] = v0.y;
            Bs[bq*8 + 2][bn] = v0.z; Bs[bq*8 + 3][bn] = v0.w;
            Bs[bq*8 + 4][bn] = v1.x; Bs[bq*8 + 5][bn] = v1.y;
            Bs[bq*8 + 6][bn] = v1.z; Bs[bq*8 + 7][bn] = v1.w;
        }
        __syncthreads();

        #pragma unroll
        for (int k = 0; k < 32; k++) {
            float4 bv = *(const float4*)&Bs[k][tx * 4];
            float afr[8];
            #pragma unroll
            for (int i = 0; i < 8; i++) afr[i] = As[ty*8 + i][k];   // broadcast
            #pragma unroll
            for (int i = 0; i < 8; i++) {
                acc[i][0] = fmaf(afr[i], bv.x, acc[i][0]);
                acc[i][1] = fmaf(afr[i], bv.y, acc[i][1]);
                acc[i][2] = fmaf(afr[i], bv.z, acc[i][2]);
                acc[i][3] = fmaf(afr[i], bv.w, acc[i][3]);
            }
        }
    }

    // store C (+bias)
    float bx = bias_s[tx*4 + 0], by = bias_s[tx*4 + 1];
    float bz = bias_s[tx*4 + 2], bw = bias_s[tx*4 + 3];
    #pragma unroll
    for (int i = 0; i < 8; i++) {
        size_t m = (size_t)(m0 + ty*8 + i);
        float4 v = make_float4(acc[i][0] + bx, acc[i][1] + by,
                               acc[i][2] + bz, acc[i][3] + bw);
        *(float4*)&g_xg1[m * G4 + n0 + tx*4] = v;
    }
}

// ---------------------------------------------------------------------------
// Launch
// ---------------------------------------------------------------------------
extern "C" void kernel_launch(void* const* d_in, const int* in_sizes, int n_in,
                              void* d_out, int out_size)
{
    const float* x      = (const float*)d_in[0];   // [256,2048,1]
    const float* W_ih0  = (const float*)d_in[1];   // [512,1]
    const float* W_hh0  = (const float*)d_in[2];   // [512,128]
    const float* b_ih0  = (const float*)d_in[3];
    const float* b_hh0  = (const float*)d_in[4];
    const float* W_ih1  = (const float*)d_in[5];   // [512,128]
    const float* W_hh1  = (const float*)d_in[6];   // [512,128]
    const float* b_ih1  = (const float*)d_in[7];
    const float* b_hh1  = (const float*)d_in[8];
    const float* W_fc   = (const float*)d_in[9];   // [1,128]
    const float* b_fc   = (const float*)d_in[10];  // [1]
    float* out = (float*)d_out;

    // Opt-in to >48KB dynamic smem. Attribute persists on the function; the
    // first (non-captured) correctness call sets it, so even if this call were
    // a no-op under capture the kernels still launch with it.
    cudaFuncSetAttribute(lstm_kernel<0>, cudaFuncAttributeMaxDynamicSharedMemorySize, SMEM_LSTM);
    cudaFuncSetAttribute(lstm_kernel<1>, cudaFuncAttributeMaxDynamicSharedMemorySize, SMEM_LSTM);

    // Layer 0 recurrence (writes g_out0, h_n[0], c_n[0])
    lstm_kernel<0><<<BATCH/2, 512, SMEM_LSTM>>>(
        x, W_ih0, W_hh0, b_ih0, b_hh0, nullptr, nullptr, out);

    // Layer 1 input gates: g_xg1 = g_out0 @ W_ih1^T + bias
    {
        dim3 grid(MROWS / 128, G4 / 64);
        gemm_xg1_kernel<<<grid, 256>>>(W_ih1, b_ih1, b_hh1);
    }

    // Layer 1 recurrence (reads g_xg1; writes h_n[1], c_n[1], y)
    lstm_kernel<1><<<BATCH/2, 512, SMEM_LSTM>>>(
        nullptr, nullptr, W_hh1, b_ih1, b_hh1, W_fc, b_fc, out);
}

// round 7
// speedup vs baseline: 1.0100x; 1.0100x over previous
#include <cuda_runtime.h>
#include <cuda_bf16.h>
#include <cstddef>
#include <math.h>

#define BATCH 256
#define TT    2048
#define HID   128
#define G4    512           // 4*HID
#define MROWS (BATCH*TT)    // 524288

typedef unsigned long long ull;

// ---- scratch (static device arrays: sanctioned allocation-free path) ----
__device__ float g_out0[(size_t)MROWS * HID];   // layer0 hidden states [B*T, 128]
__device__ float g_xg1 [(size_t)MROWS * G4];    // layer1 input gates (+bias) [B*T, 512]

// ---------------- packed f32x2 helpers (sm_103a) ----------------
__device__ __forceinline__ ull pk2(float lo, float hi) {
    ull r; asm("mov.b64 %0, {%1, %2};" : "=l"(r) : "f"(lo), "f"(hi)); return r;
}
__device__ __forceinline__ float2 upk(ull v) {
    float2 r; asm("mov.b64 {%0, %1}, %2;" : "=f"(r.x), "=f"(r.y) : "l"(v)); return r;
}
__device__ __forceinline__ void ffma2(ull& d, ull a, ull b) {
    asm("fma.rn.f32x2 %0, %1, %2, %0;" : "+l"(d) : "l"(a), "l"(b));
}

// ---------------- fast activations ----------------
__device__ __forceinline__ float sigm_f(float v) {
    float e = __expf(-v);                 // FMUL + MUFU.EX2
    return __fdividef(1.0f, 1.0f + e);    // inf -> 0, 0 -> 1 : correct tails
}
__device__ __forceinline__ float tanh_f(float v) {
    float e = __expf(2.0f * v);           // 0 -> -1, inf -> +1 : correct tails
    return 1.0f - __fdividef(2.0f, 1.0f + e);
}

// ---------------------------------------------------------------------------
// Recurrent LSTM layer. 128 CTAs x 512 threads; CTA owns batch rows 2*bx,2*bx+1.
// Thread g computes gate-row g for both rows, K-packed f32x2:
//   acc = packed (even-k, odd-k) partial sums; weights/h load as adjacent pairs.
// W_hh cols [0,64) in smem as ulonglong2 k-major (LDS.128, conflict-free),
// cols [64,128) in 16 ulonglong2 registers. Two __syncthreads per step.
// ---------------------------------------------------------------------------
#define KSMC 16   // smem weight chunks of 4 floats (k 0..63)
#define KRGC 16   // register weight chunks of 4 floats (k 64..127)
#define SMEM_LSTM (KSMC*G4*16 /*WsmU*/ + 2*HID*4 /*h*/ + 2*G4*4 /*gates*/)

template<int LAYER>
__global__ void __launch_bounds__(512, 1)
lstm_kernel(const float* __restrict__ x,     // layer0: [B,T,1]
            const float* __restrict__ W_ih,  // layer0: [512,1]
            const float* __restrict__ W_hh,  // [512,128]
            const float* __restrict__ b_ih,
            const float* __restrict__ b_hh,
            const float* __restrict__ W_fc,  // layer1: [1,128]
            const float* __restrict__ b_fc,  // layer1: [1]
            float* __restrict__ out)
{
    extern __shared__ ulonglong2 smem_u2[];
    ulonglong2* WsmU   = smem_u2;                       // [16][512]
    float*      h_sm   = (float*)(smem_u2 + KSMC * G4); // [2][128] (16B aligned)
    float*      gate_sm= h_sm + 2 * HID;                // [2][512]

    const int g  = threadIdx.x;
    const int b0 = blockIdx.x * 2;

    // ---- weight staging ----
    const ulonglong2* wrow = (const ulonglong2*)(W_hh + (size_t)g * HID); // 32 chunks
    #pragma unroll 4
    for (int j = 0; j < KSMC; j++)
        WsmU[j * G4 + g] = wrow[j];          // k 0..63 -> smem, k-major
    ulonglong2 wreg2[KRGC];
    #pragma unroll
    for (int j = 0; j < KRGC; j++)
        wreg2[j] = wrow[KSMC + j];           // k 64..127 -> registers

    float wih = 0.f, bias = 0.f;
    if (LAYER == 0) {
        wih  = __ldg(&W_ih[g]);
        bias = __ldg(&b_ih[g]) + __ldg(&b_hh[g]);
    }

    if (g < 2 * HID) h_sm[g] = 0.f;
    float c = 0.f;                            // cell state (update threads g<256)
    __syncthreads();

    const ulonglong2* hp0 = (const ulonglong2*)h_sm;            // 32 chunks
    const ulonglong2* hp1 = (const ulonglong2*)(h_sm + HID);
    const int ub = g >> 7;                    // update thread: batch slot (g<256)
    const int uj = g & (HID - 1);
    const int gclass = g >> 7;                // 0:i 1:f 2:g 3:o (warp-uniform)

    for (int t = 0; t < TT; t++) {
        // --- input-gate contribution (issued early, consumed after the dot) ---
        float xg0, xg1v;
        if (LAYER == 0) {
            float xv0 = __ldg(&x[(size_t)b0 * TT + t]);
            float xv1 = __ldg(&x[(size_t)(b0 + 1) * TT + t]);
            xg0  = fmaf(wih, xv0, bias);
            xg1v = fmaf(wih, xv1, bias);
        } else {
            xg0  = __ldg(&g_xg1[((size_t)b0 * TT + t) * G4 + g]);
            xg1v = __ldg(&g_xg1[((size_t)(b0 + 1) * TT + t) * G4 + g]);
        }

        // --- recurrent dot, K-packed f32x2, 2 chains per row ---
        ull a0a = pk2(xg0, 0.f),  a0b = pk2(0.f, 0.f);
        ull a1a = pk2(xg1v, 0.f), a1b = pk2(0.f, 0.f);

        #pragma unroll
        for (int j = 0; j < KSMC; j += 2) {               // k 0..63 from smem
            ulonglong2 wA = WsmU[j * G4 + g];
            ulonglong2 wB = WsmU[(j + 1) * G4 + g];
            ulonglong2 h0A = hp0[j], h0B = hp0[j + 1];
            ulonglong2 h1A = hp1[j], h1B = hp1[j + 1];
            ffma2(a0a, wA.x, h0A.x); ffma2(a0a, wA.y, h0A.y);
            ffma2(a0b, wB.x, h0B.x); ffma2(a0b, wB.y, h0B.y);
            ffma2(a1a, wA.x, h1A.x); ffma2(a1a, wA.y, h1A.y);
            ffma2(a1b, wB.x, h1B.x); ffma2(a1b, wB.y, h1B.y);
        }
        #pragma unroll
        for (int j = 0; j < KRGC; j += 2) {               // k 64..127 from regs
            ulonglong2 wA = wreg2[j];
            ulonglong2 wB = wreg2[j + 1];
            ulonglong2 h0A = hp0[KSMC + j], h0B = hp0[KSMC + j + 1];
            ulonglong2 h1A = hp1[KSMC + j], h1B = hp1[KSMC + j + 1];
            ffma2(a0a, wA.x, h0A.x); ffma2(a0a, wA.y, h0A.y);
            ffma2(a0b, wB.x, h0B.x); ffma2(a0b, wB.y, h0B.y);
            ffma2(a1a, wA.x, h1A.x); ffma2(a1a, wA.y, h1A.y);
            ffma2(a1b, wB.x, h1B.x); ffma2(a1b, wB.y, h1B.y);
        }

        float2 f0a = upk(a0a), f0b = upk(a0b);
        float2 f1a = upk(a1a), f1b = upk(a1b);
        float a0 = (f0a.x + f0a.y) + (f0b.x + f0b.y);
        float a1 = (f1a.x + f1a.y) + (f1b.x + f1b.y);

        // --- activation (i,f,o: sigmoid; g: tanh) ---
        float act0, act1;
        if (gclass == 2) { act0 = tanh_f(a0); act1 = tanh_f(a1); }
        else             { act0 = sigm_f(a0); act1 = sigm_f(a1); }
        gate_sm[g]      = act0;
        gate_sm[G4 + g] = act1;
        __syncthreads();

        // --- cell/hidden update (threads 0..255 own (ub, uj)) ---
        if (g < 2 * HID) {
            const float* gb = gate_sm + ub * G4;
            float iv = gb[uj];
            float fv = gb[HID + uj];
            float gv = gb[2 * HID + uj];
            float ov = gb[3 * HID + uj];
            c = fmaf(fv, c, iv * gv);
            float h = ov * tanh_f(c);
            h_sm[ub * HID + uj] = h;
            if (LAYER == 0)
                g_out0[((size_t)(b0 + ub) * TT + t) * HID + uj] = h;
        }
        __syncthreads();
    }

    // --- final h_n / c_n. out layout: y[256] | h_n[2][256][128] | c_n[2][256][128]
    if (g < 2 * HID) {
        int bglob = b0 + ub;
        out[256 + ((size_t)LAYER * BATCH + bglob) * HID + uj] = h_sm[ub * HID + uj];
        out[256 + (size_t)2 * BATCH * HID
                + ((size_t)LAYER * BATCH + bglob) * HID + uj] = c;
    }

    // --- FC head (layer 1 only): y[b] = h_final[b] . W_fc + b_fc ---
    if (LAYER == 1 && g < 64) {
        int w = g >> 5;          // batch slot 0/1
        int l = g & 31;
        float s = 0.f;
        #pragma unroll
        for (int j = l; j < HID; j += 32)
            s = fmaf(h_sm[w * HID + j], __ldg(&W_fc[j]), s);
        #pragma unroll
        for (int off = 16; off > 0; off >>= 1)
            s += __shfl_down_sync(0xffffffffu, s, off);
        if (l == 0)
            out[b0 + w] = s + __ldg(&b_fc[0]);
    }
}

// ---------------------------------------------------------------------------
// GEMM: g_xg1[M,512] = g_out0[M,128] @ W_ih1^T + (b_ih1 + b_hh1)
// Tiles 128(M) x 64(N), K-chunks of 32. 256 threads. f32x2 M-packed:
// A stored transposed [k][m] (adjacent-m pairs load as packed f32x2),
// B stored pre-duplicated (w,w) as ull. 16 FFMA2 + 4 LDS.128 per k-iter.
// ---------------------------------------------------------------------------
__global__ void __launch_bounds__(256)
gemm_xg1_kernel(const float* __restrict__ W,     // W_ih_l1 [512,128]
                const float* __restrict__ b_ih,
                const float* __restrict__ b_hh)
{
    __shared__ __align__(16) float At[32][132];  // [k][m], +4 pad
    __shared__ __align__(16) ull   Bs2[32][64];  // duplicated (w,w)
    __shared__ float bias_s[64];

    const int tid = threadIdx.x;
    const int m0 = blockIdx.x * 128;
    const int n0 = blockIdx.y * 64;

    if (tid < 64)
        bias_s[tid] = __ldg(&b_ih[n0 + tid]) + __ldg(&b_hh[n0 + tid]);

    const int tx = tid & 15;        // N dir: cols tx*4 .. +3
    const int ty = tid >> 4;        // M dir: rows ty*8 .. +7 (4 packed pairs)

    const int ar = tid >> 1;        // A load: m row 0..127
    const int ah = (tid & 1) * 16;  // A load: k offset 0/16 within chunk
    const int bn = tid & 63;        // B load: n row 0..63
    const int bq = tid >> 6;        // B load: k-quarter 0..3

    ull acc[4][4];                  // [m-pair][n]
    #pragma unroll
    for (int i = 0; i < 4; i++)
        #pragma unroll
        for (int j = 0; j < 4; j++) acc[i][j] = pk2(0.f, 0.f);

    for (int kc = 0; kc < 128; kc += 32) {
        __syncthreads();
        {   // A chunk: 128 m x 32 k, store transposed [k][m]
            const float4* ap = (const float4*)(g_out0 + (size_t)(m0 + ar) * HID + kc + ah);
            float4 v0 = ap[0], v1 = ap[1], v2 = ap[2], v3 = ap[3];
            At[ah + 0][ar] = v0.x; At[ah + 1][ar] = v0.y; At[ah + 2][ar] = v0.z; At[ah + 3][ar] = v0.w;
            At[ah + 4][ar] = v1.x; At[ah + 5][ar] = v1.y; At[ah + 6][ar] = v1.z; At[ah + 7][ar] = v1.w;
            At[ah + 8][ar] = v2.x; At[ah + 9][ar] = v2.y; At[ah +10][ar] = v2.z; At[ah +11][ar] = v2.w;
            At[ah +12][ar] = v3.x; At[ah +13][ar] = v3.y; At[ah +14][ar] = v3.z; At[ah +15][ar] = v3.w;
        }
        {   // B chunk: 64 n x 32 k, duplicated (w,w)
            const float4* bp = (const float4*)(W + (size_t)(n0 + bn) * HID + kc + bq * 8);
            float4 v0 = bp[0], v1 = bp[1];
            Bs2[bq*8 + 0][bn] = pk2(v0.x, v0.x); Bs2[bq*8 + 1][bn] = pk2(v0.y, v0.y);
            Bs2[bq*8 + 2][bn] = pk2(v0.z, v0.z); Bs2[bq*8 + 3][bn] = pk2(v0.w, v0.w);
            Bs2[bq*8 + 4][bn] = pk2(v1.x, v1.x); Bs2[bq*8 + 5][bn] = pk2(v1.y, v1.y);
            Bs2[bq*8 + 6][bn] = pk2(v1.z, v1.z); Bs2[bq*8 + 7][bn] = pk2(v1.w, v1.w);
        }
        __syncthreads();

        #pragma unroll
        for (int k = 0; k < 32; k++) {
            ulonglong2 a01 = *(const ulonglong2*)&At[k][ty * 8];      // pairs (m0,m1),(m2,m3)
            ulonglong2 a23 = *(const ulonglong2*)&At[k][ty * 8 + 4];  // pairs (m4,m5),(m6,m7)
            ulonglong2 b01 = *(const ulonglong2*)&Bs2[k][tx * 4];     // dup n0, n1
            ulonglong2 b23 = *(const ulonglong2*)&Bs2[k][tx * 4 + 2]; // dup n2, n3
            ffma2(acc[0][0], a01.x, b01.x); ffma2(acc[0][1], a01.x, b01.y);
            ffma2(acc[0][2], a01.x, b23.x); ffma2(acc[0][3], a01.x, b23.y);
            ffma2(acc[1][0], a01.y, b01.x); ffma2(acc[1][1], a01.y, b01.y);
            ffma2(acc[1][2], a01.y, b23.x); ffma2(acc[1][3], a01.y, b23.y);
            ffma2(acc[2][0], a23.x, b01.x); ffma2(acc[2][1], a23.x, b01.y);
            ffma2(acc[2][2], a23.x, b23.x); ffma2(acc[2][3], a23.x, b23.y);
            ffma2(acc[3][0], a23.y, b01.x); ffma2(acc[3][1], a23.y, b01.y);
            ffma2(acc[3][2], a23.y, b23.x); ffma2(acc[3][3], a23.y, b23.y);
        }
    }

    // store C (+bias): unpack pairs -> rows ty*8+2*mp (lo) and +1 (hi)
    float bx = bias_s[tx*4 + 0], by = bias_s[tx*4 + 1];
    float bz = bias_s[tx*4 + 2], bw = bias_s[tx*4 + 3];
    #pragma unroll
    for (int mp = 0; mp < 4; mp++) {
        float2 c0 = upk(acc[mp][0]), c1 = upk(acc[mp][1]);
        float2 c2 = upk(acc[mp][2]), c3 = upk(acc[mp][3]);
        size_t mA = (size_t)(m0 + ty * 8 + 2 * mp);
        float4 vA = make_float4(c0.x + bx, c1.x + by, c2.x + bz, c3.x + bw);
        float4 vB = make_float4(c0.y + bx, c1.y + by, c2.y + bz, c3.y + bw);
        *(float4*)&g_xg1[mA * G4 + n0 + tx * 4]       = vA;
        *(float4*)&g_xg1[(mA + 1) * G4 + n0 + tx * 4] = vB;
    }
}

// ---------------------------------------------------------------------------
// Launch
// ---------------------------------------------------------------------------
extern "C" void kernel_launch(void* const* d_in, const int* in_sizes, int n_in,
                              void* d_out, int out_size)
{
    const float* x      = (const float*)d_in[0];   // [256,2048,1]
    const float* W_ih0  = (const float*)d_in[1];   // [512,1]
    const float* W_hh0  = (const float*)d_in[2];   // [512,128]
    const float* b_ih0  = (const float*)d_in[3];
    const float* b_hh0  = (const float*)d_in[4];
    const float* W_ih1  = (const float*)d_in[5];   // [512,128]
    const float* W_hh1  = (const float*)d_in[6];   // [512,128]
    const float* b_ih1  = (const float*)d_in[7];
    const float* b_hh1  = (const float*)d_in[8];
    const float* W_fc   = (const float*)d_in[9];   // [1,128]
    const float* b_fc   = (const float*)d_in[10];  // [1]
    float* out = (float*)d_out;

    cudaFuncSetAttribute(lstm_kernel<0>, cudaFuncAttributeMaxDynamicSharedMemorySize, SMEM_LSTM);
    cudaFuncSetAttribute(lstm_kernel<1>, cudaFuncAttributeMaxDynamicSharedMemorySize, SMEM_LSTM);

    // Layer 0 recurrence (writes g_out0, h_n[0], c_n[0])
    lstm_kernel<0><<<BATCH/2, 512, SMEM_LSTM>>>(
        x, W_ih0, W_hh0, b_ih0, b_hh0, nullptr, nullptr, out);

    // Layer 1 input gates: g_xg1 = g_out0 @ W_ih1^T + bias
    {
        dim3 grid(MROWS / 128, G4 / 64);
        gemm_xg1_kernel<<<grid, 256>>>(W_ih1, b_ih1, b_hh1);
    }

    // Layer 1 recurrence (reads g_xg1; writes h_n[1], c_n[1], y)
    lstm_kernel<1><<<BATCH/2, 512, SMEM_LSTM>>>(
        nullptr, nullptr, W_hh1, b_ih1, b_hh1, W_fc, b_fc, out);
}

// round 8
// speedup vs baseline: 1.3902x; 1.3764x over previous
#include <cuda_runtime.h>
#include <cuda_bf16.h>
#include <cstddef>
#include <math.h>

#define BATCH 256
#define TT    2048
#define HID   128
#define G4    512           // 4*HID
#define MROWS (BATCH*TT)    // 524288

typedef unsigned long long ull;

// ---- scratch (static device arrays: sanctioned allocation-free path) ----
__device__ float g_out0[(size_t)MROWS * HID];   // layer0 hidden states [B*T, 128]
__device__ float g_xg1 [(size_t)MROWS * G4];    // layer1 input gates (+bias) [B*T, 512]

// ---------------- packed f32x2 helpers (sm_103a) ----------------
__device__ __forceinline__ ull pk2(float lo, float hi) {
    ull r; asm("mov.b64 %0, {%1, %2};" : "=l"(r) : "f"(lo), "f"(hi)); return r;
}
__device__ __forceinline__ float2 upk(ull v) {
    float2 r; asm("mov.b64 {%0, %1}, %2;" : "=f"(r.x), "=f"(r.y) : "l"(v)); return r;
}
__device__ __forceinline__ void ffma2(ull& d, ull a, ull b) {
    asm("fma.rn.f32x2 %0, %1, %2, %0;" : "+l"(d) : "l"(a), "l"(b));
}

// ---------------- fast activations ----------------
__device__ __forceinline__ float sigm_f(float v) {
    float e = __expf(-v);
    return __fdividef(1.0f, 1.0f + e);    // inf -> 0, 0 -> 1 : correct tails
}
__device__ __forceinline__ float tanh_f(float v) {
    float e = __expf(2.0f * v);           // 0 -> -1, inf -> +1 : correct tails
    return 1.0f - __fdividef(2.0f, 1.0f + e);
}

// shared dynamic smem symbol for all kernels
extern __shared__ __align__(16) unsigned char dynsm[];

// ---------------------------------------------------------------------------
// LSTM layer. 128 CTAs x 256 threads; CTA owns batch rows 2*bx, 2*bx+1.
// Thread owns gate rows r0 = tid (weights in SMEM, k-major ulonglong2,
// conflict-free LDS.128) and r1 = tid+256 (weights fully in 128 registers),
// for BOTH batch rows -> 4 dots/thread/step. Each h-broadcast chunk feeds
// 4 ffma2 (reuse 4x vs R7's 1x). Two __syncthreads per step.
// ---------------------------------------------------------------------------
#define SMEM_LSTM (32*256*16 /*Wsm*/ + 2*HID*4 /*h*/ + 2*G4*4 /*gates*/)

template<int LAYER>
__global__ void __launch_bounds__(256, 1)
lstm_kernel(const float* __restrict__ x,     // layer0: [B,T,1]
            const float* __restrict__ W_ih,  // layer0: [512,1]
            const float* __restrict__ W_hh,  // [512,128]
            const float* __restrict__ b_ih,
            const float* __restrict__ b_hh,
            const float* __restrict__ W_fc,  // layer1: [1,128]
            const float* __restrict__ b_fc,  // layer1: [1]
            float* __restrict__ out)
{
    ulonglong2* Wsm    = (ulonglong2*)dynsm;            // [32][256]
    float*      h_sm   = (float*)(dynsm + 32*256*16);   // [2][128]
    float*      gate_sm= h_sm + 2 * HID;                // [2][512]

    const int tid = threadIdx.x;
    const int b0  = blockIdx.x * 2;
    const int r0  = tid;
    const int r1  = 256 + tid;

    // ---- weight staging: row r0 -> smem (k-major), row r1 -> registers ----
    const ulonglong2* w0p = (const ulonglong2*)(W_hh + (size_t)r0 * HID);
    const ulonglong2* w1p = (const ulonglong2*)(W_hh + (size_t)r1 * HID);
    ulonglong2 wreg[32];
    #pragma unroll
    for (int j = 0; j < 32; j++) {
        Wsm[j * 256 + tid] = w0p[j];
        wreg[j] = w1p[j];
    }

    float wih0 = 0.f, wih1 = 0.f, bias0 = 0.f, bias1 = 0.f;
    if (LAYER == 0) {
        wih0  = __ldg(&W_ih[r0]);
        wih1  = __ldg(&W_ih[r1]);
        bias0 = __ldg(&b_ih[r0]) + __ldg(&b_hh[r0]);
        bias1 = __ldg(&b_ih[r1]) + __ldg(&b_hh[r1]);
    }

    h_sm[tid] = 0.f;           // tid covers [0, 2*HID)
    float c = 0.f;             // cell state: thread owns (ub, uj)
    __syncthreads();

    const ulonglong2* hp0 = (const ulonglong2*)h_sm;          // 32 chunks
    const ulonglong2* hp1 = (const ulonglong2*)(h_sm + HID);
    const int ub = tid >> 7;           // batch slot 0/1
    const int uj = tid & (HID - 1);    // hidden index

    for (int t = 0; t < TT; t++) {
        // --- input-gate contributions for (row, batch) pairs ---
        float xg00, xg01, xg10, xg11;
        if (LAYER == 0) {
            float xv0 = __ldg(&x[(size_t)b0 * TT + t]);
            float xv1 = __ldg(&x[(size_t)(b0 + 1) * TT + t]);
            xg00 = fmaf(wih0, xv0, bias0);
            xg01 = fmaf(wih0, xv1, bias0);
            xg10 = fmaf(wih1, xv0, bias1);
            xg11 = fmaf(wih1, xv1, bias1);
        } else {
            const float* p0 = g_xg1 + ((size_t)b0 * TT + t) * G4;
            const float* p1 = g_xg1 + ((size_t)(b0 + 1) * TT + t) * G4;
            xg00 = __ldg(p0 + r0);
            xg01 = __ldg(p1 + r0);
            xg10 = __ldg(p0 + r1);
            xg11 = __ldg(p1 + r1);
        }

        // --- 4 dots of length 128, K-packed f32x2, 2 chains each ---
        ull a00a = pk2(xg00, 0.f), a00b = pk2(0.f, 0.f);
        ull a01a = pk2(xg01, 0.f), a01b = pk2(0.f, 0.f);
        ull a10a = pk2(xg10, 0.f), a10b = pk2(0.f, 0.f);
        ull a11a = pk2(xg11, 0.f), a11b = pk2(0.f, 0.f);

        #pragma unroll
        for (int j = 0; j < 32; j++) {
            ulonglong2 wA = Wsm[j * 256 + tid];   // row r0 weights (smem)
            ulonglong2 h0 = hp0[j];               // broadcast
            ulonglong2 h1 = hp1[j];               // broadcast
            ulonglong2 wB = wreg[j];              // row r1 weights (regs)
            ffma2(a00a, wA.x, h0.x); ffma2(a00b, wA.y, h0.y);
            ffma2(a01a, wA.x, h1.x); ffma2(a01b, wA.y, h1.y);
            ffma2(a10a, wB.x, h0.x); ffma2(a10b, wB.y, h0.y);
            ffma2(a11a, wB.x, h1.x); ffma2(a11b, wB.y, h1.y);
        }

        float2 f;
        f = upk(a00a); float a00 = f.x + f.y; f = upk(a00b); a00 += f.x + f.y;
        f = upk(a01a); float a01 = f.x + f.y; f = upk(a01b); a01 += f.x + f.y;
        f = upk(a10a); float a10 = f.x + f.y; f = upk(a10b); a10 += f.x + f.y;
        f = upk(a11a); float a11 = f.x + f.y; f = upk(a11b); a11 += f.x + f.y;

        // --- activations: r0 is i (tid<128) or f -> sigmoid;
        //                  r1 is g (tid<128) -> tanh, else o -> sigmoid ---
        float g00 = sigm_f(a00);
        float g01 = sigm_f(a01);
        float g10, g11;
        if (tid < 128) { g10 = tanh_f(a10); g11 = tanh_f(a11); }
        else           { g10 = sigm_f(a10); g11 = sigm_f(a11); }

        gate_sm[r0]      = g00;
        gate_sm[G4 + r0] = g01;
        gate_sm[r1]      = g10;
        gate_sm[G4 + r1] = g11;
        __syncthreads();

        // --- cell/hidden update: all 256 threads, thread owns (ub, uj) ---
        {
            const float* gb = gate_sm + ub * G4;
            float iv = gb[uj];
            float fv = gb[HID + uj];
            float gv = gb[2 * HID + uj];
            float ov = gb[3 * HID + uj];
            c = fmaf(fv, c, iv * gv);
            float h = ov * tanh_f(c);
            h_sm[tid] = h;                         // tid == ub*HID + uj
            if (LAYER == 0)
                g_out0[((size_t)(b0 + ub) * TT + t) * HID + uj] = h;
        }
        __syncthreads();
    }

    // --- final h_n / c_n. out layout: y[256] | h_n[2][256][128] | c_n[2][256][128]
    {
        int bglob = b0 + ub;
        out[256 + ((size_t)LAYER * BATCH + bglob) * HID + uj] = h_sm[tid];
        out[256 + (size_t)2 * BATCH * HID
                + ((size_t)LAYER * BATCH + bglob) * HID + uj] = c;
    }

    // --- FC head (layer 1 only): y[b] = h_final[b] . W_fc + b_fc ---
    if (LAYER == 1 && tid < 64) {
        int w = tid >> 5;          // batch slot 0/1
        int l = tid & 31;
        float s = 0.f;
        #pragma unroll
        for (int j = l; j < HID; j += 32)
            s = fmaf(h_sm[w * HID + j], __ldg(&W_fc[j]), s);
        #pragma unroll
        for (int off = 16; off > 0; off >>= 1)
            s += __shfl_down_sync(0xffffffffu, s, off);
        if (l == 0)
            out[b0 + w] = s + __ldg(&b_fc[0]);
    }
}

// ---------------------------------------------------------------------------
// GEMM: g_xg1[M,512] = g_out0[M,128] @ W_ih1^T + (b_ih1 + b_hh1)
// Single K=128 pass (one sync), tiles 128(M) x 64(N), 256 threads,
// dynamic smem: At [128k][132m] transposed + Bs [128k][64n] plain.
// f32x2 M-packed compute: per k-iter 3 LDS.128 + 4 dup-movs + 16 FFMA2.
// Grid x = n-tile (fastest) so the 8 n-tiles sharing an A tile hit L2.
// ---------------------------------------------------------------------------
#define AT_LD 132
#define SMEM_GEMM ((128*AT_LD + 128*64 + 64) * 4)

__global__ void __launch_bounds__(256, 2)
gemm_xg1_kernel(const float* __restrict__ W,     // W_ih_l1 [512,128]
                const float* __restrict__ b_ih,
                const float* __restrict__ b_hh)
{
    float* At     = (float*)dynsm;            // [128][132]
    float* Bs     = At + 128 * AT_LD;         // [128][64]
    float* bias_s = Bs + 128 * 64;            // [64]

    const int tid = threadIdx.x;
    const int n0  = blockIdx.x * 64;
    const int m0  = blockIdx.y * 128;

    if (tid < 64)
        bias_s[tid] = __ldg(&b_ih[n0 + tid]) + __ldg(&b_hh[n0 + tid]);

    // load A: 128m x 128k -> transposed [k][m]. Thread: m-row ar, k half ak.
    {
        const int ar = tid >> 1;
        const int ak = (tid & 1) * 64;
        const float4* ap = (const float4*)(g_out0 + (size_t)(m0 + ar) * HID + ak);
        #pragma unroll
        for (int q = 0; q < 16; q++) {
            float4 v = ap[q];
            At[(ak + q*4 + 0) * AT_LD + ar] = v.x;
            At[(ak + q*4 + 1) * AT_LD + ar] = v.y;
            At[(ak + q*4 + 2) * AT_LD + ar] = v.z;
            At[(ak + q*4 + 3) * AT_LD + ar] = v.w;
        }
    }
    // load B: 64n x 128k -> [k][n]. Thread: n-row bn, k quarter bk.
    {
        const int bn = tid & 63;
        const int bk = (tid >> 6) * 32;
        const float4* bp = (const float4*)(W + (size_t)(n0 + bn) * HID + bk);
        #pragma unroll
        for (int q = 0; q < 8; q++) {
            float4 v = bp[q];
            Bs[(bk + q*4 + 0) * 64 + bn] = v.x;
            Bs[(bk + q*4 + 1) * 64 + bn] = v.y;
            Bs[(bk + q*4 + 2) * 64 + bn] = v.z;
            Bs[(bk + q*4 + 3) * 64 + bn] = v.w;
        }
    }
    __syncthreads();

    const int tx = tid & 15;   // n cols tx*4 .. +3
    const int ty = tid >> 4;   // m rows ty*8 .. +7 (4 packed pairs)

    ull acc[4][4];
    #pragma unroll
    for (int i = 0; i < 4; i++)
        #pragma unroll
        for (int j = 0; j < 4; j++) acc[i][j] = pk2(0.f, 0.f);

    #pragma unroll 8
    for (int k = 0; k < 128; k++) {
        ulonglong2 a01 = *(const ulonglong2*)&At[k * AT_LD + ty * 8];
        ulonglong2 a23 = *(const ulonglong2*)&At[k * AT_LD + ty * 8 + 4];
        float4 bv = *(const float4*)&Bs[k * 64 + tx * 4];
        ull b0d = pk2(bv.x, bv.x);
        ull b1d = pk2(bv.y, bv.y);
        ull b2d = pk2(bv.z, bv.z);
        ull b3d = pk2(bv.w, bv.w);
        ffma2(acc[0][0], a01.x, b0d); ffma2(acc[0][1], a01.x, b1d);
        ffma2(acc[0][2], a01.x, b2d); ffma2(acc[0][3], a01.x, b3d);
        ffma2(acc[1][0], a01.y, b0d); ffma2(acc[1][1], a01.y, b1d);
        ffma2(acc[1][2], a01.y, b2d); ffma2(acc[1][3], a01.y, b3d);
        ffma2(acc[2][0], a23.x, b0d); ffma2(acc[2][1], a23.x, b1d);
        ffma2(acc[2][2], a23.x, b2d); ffma2(acc[2][3], a23.x, b3d);
        ffma2(acc[3][0], a23.y, b0d); ffma2(acc[3][1], a23.y, b1d);
        ffma2(acc[3][2], a23.y, b2d); ffma2(acc[3][3], a23.y, b3d);
    }

    // store C (+bias): unpack pairs -> rows ty*8+2*mp (lo) and +1 (hi)
    float bx = bias_s[tx*4 + 0], by = bias_s[tx*4 + 1];
    float bz = bias_s[tx*4 + 2], bw = bias_s[tx*4 + 3];
    #pragma unroll
    for (int mp = 0; mp < 4; mp++) {
        float2 c0 = upk(acc[mp][0]), c1 = upk(acc[mp][1]);
        float2 c2 = upk(acc[mp][2]), c3 = upk(acc[mp][3]);
        size_t mA = (size_t)(m0 + ty * 8 + 2 * mp);
        float4 vA = make_float4(c0.x + bx, c1.x + by, c2.x + bz, c3.x + bw);
        float4 vB = make_float4(c0.y + bx, c1.y + by, c2.y + bz, c3.y + bw);
        *(float4*)&g_xg1[mA * G4 + n0 + tx * 4]       = vA;
        *(float4*)&g_xg1[(mA + 1) * G4 + n0 + tx * 4] = vB;
    }
}

// ---------------------------------------------------------------------------
// Launch
// ---------------------------------------------------------------------------
extern "C" void kernel_launch(void* const* d_in, const int* in_sizes, int n_in,
                              void* d_out, int out_size)
{
    const float* x      = (const float*)d_in[0];   // [256,2048,1]
    const float* W_ih0  = (const float*)d_in[1];   // [512,1]
    const float* W_hh0  = (const float*)d_in[2];   // [512,128]
    const float* b_ih0  = (const float*)d_in[3];
    const float* b_hh0  = (const float*)d_in[4];
    const float* W_ih1  = (const float*)d_in[5];   // [512,128]
    const float* W_hh1  = (const float*)d_in[6];   // [512,128]
    const float* b_ih1  = (const float*)d_in[7];
    const float* b_hh1  = (const float*)d_in[8];
    const float* W_fc   = (const float*)d_in[9];   // [1,128]
    const float* b_fc   = (const float*)d_in[10];  // [1]
    float* out = (float*)d_out;

    cudaFuncSetAttribute(lstm_kernel<0>, cudaFuncAttributeMaxDynamicSharedMemorySize, SMEM_LSTM);
    cudaFuncSetAttribute(lstm_kernel<1>, cudaFuncAttributeMaxDynamicSharedMemorySize, SMEM_LSTM);
    cudaFuncSetAttribute(gemm_xg1_kernel, cudaFuncAttributeMaxDynamicSharedMemorySize, SMEM_GEMM);

    // Layer 0 recurrence (writes g_out0, h_n[0], c_n[0])
    lstm_kernel<0><<<BATCH/2, 256, SMEM_LSTM>>>(
        x, W_ih0, W_hh0, b_ih0, b_hh0, nullptr, nullptr, out);

    // Layer 1 input gates: g_xg1 = g_out0 @ W_ih1^T + bias
    {
        dim3 grid(G4 / 64, MROWS / 128);   // x = n-tile fastest (A-tile L2 reuse)
        gemm_xg1_kernel<<<grid, 256, SMEM_GEMM>>>(W_ih1, b_ih1, b_hh1);
    }

    // Layer 1 recurrence (reads g_xg1; writes h_n[1], c_n[1], y)
    lstm_kernel<1><<<BATCH/2, 256, SMEM_LSTM>>>(
        nullptr, nullptr, W_hh1, b_ih1, b_hh1, W_fc, b_fc, out);
}